// round 3
// baseline (speedup 1.0000x reference)
#include <cuda_runtime.h>

#define HID   50
#define SEQT  512
#define NB    5          // batch elements per block
#define BLOCK 512        // NB * HID * 2 = 500 active threads

// packed 2xfp32 FMA: d = a*b + c (elementwise on two floats in a 64-bit reg)
__device__ __forceinline__ unsigned long long fma2(unsigned long long a,
                                                   unsigned long long b,
                                                   unsigned long long c) {
    unsigned long long d;
    asm("fma.rn.f32x2 %0, %1, %2, %3;" : "=l"(d) : "l"(a), "l"(b), "l"(c));
    return d;
}
__device__ __forceinline__ float hsum2(unsigned long long v) {
    float lo, hi;
    asm("mov.b64 {%0, %1}, %2;" : "=f"(lo), "=f"(hi) : "l"(v));
    return lo + hi;
}
__device__ __forceinline__ float tanhapx(float x) {
    float y;
    asm("tanh.approx.f32 %0, %1;" : "=f"(y) : "f"(x));
    return y;
}
__device__ __forceinline__ float sigapx(float x) {
    // sigmoid(x) = 0.5*tanh(x/2) + 0.5   (1 MUFU + 2 FFMA)
    return __fmaf_rn(0.5f, tanhapx(0.5f * x), 0.5f);
}

__global__ void __launch_bounds__(BLOCK, 1)
lstm_fused_kernel(const float* __restrict__ x,
                  const float* __restrict__ W_ih,
                  const float* __restrict__ W_hh,
                  const float* __restrict__ b_ih,
                  const float* __restrict__ b_hh,
                  const float* __restrict__ W_out,
                  const float* __restrict__ b_out,
                  float* __restrict__ out,
                  int B)
{
    // double-buffered hidden state, rows padded to 52 floats (208B = 13*16B)
    __shared__ __align__(16) float sh_h[2][NB][52];
    __shared__ __align__(16) float sh_wout[52];

    const int tid = threadIdx.x;
    int bl = tid / 100;              // local batch index 0..5 (5 == filler)
    int r  = tid - bl * 100;         // 0..99 within batch element
    const bool lane_ok = (bl < NB);
    if (!lane_ok) { bl = 0; r = 0; } // clamp for safe addressing
    const int j  = r >> 1;           // hidden unit 0..49
    const int gp = tid & 1;          // gate pair: 0 -> {i,f}, 1 -> {g,o}
    const int b = blockIdx.x * NB + bl;
    const bool active = lane_ok && (b < B);
    const int bb = active ? b : 0;

    // ---- one-time init ----
    for (int i = tid; i < 2 * NB * 52; i += BLOCK)
        (&sh_h[0][0][0])[i] = 0.0f;
    if (tid < 52)
        sh_wout[tid] = (tid < HID) ? W_out[tid] : 0.0f;

    // W_hh rows for this thread's 2 gates, packed as f32 pairs (64-bit regs).
    // Row byte offset = row*200 -> 8B aligned, direct 64-bit loads.
    unsigned long long w2[2][25];
    float wih[2], bs[2];
    #pragma unroll
    for (int g = 0; g < 2; g++) {
        const int row = (gp * 2 + g) * HID + j;   // gate order: i, f, g, o
        wih[g] = W_ih[row];
        bs[g]  = b_ih[row] + b_hh[row];
        const unsigned long long* wrow =
            reinterpret_cast<const unsigned long long*>(W_hh + row * HID);
        #pragma unroll
        for (int p = 0; p < 25; p++)
            w2[g][p] = wrow[p];
    }
    const float bout = b_out[0];

    const float* __restrict__ xrow = x   + (size_t)bb * SEQT;
    float*       __restrict__ orow = out + (size_t)bb * SEQT;

    float c  = 0.0f;                 // cell state lives in even (gp==0) thread
    float xt = xrow[0];
    int cur = 0;

    __syncthreads();   // h buffer zeroed, wout staged

    for (int t = 0; t < SEQT; t++) {
        unsigned long long acc0 = 0ull, acc1 = 0ull;

        // prefetch next x (hidden behind the dot product)
        float xnext = (t + 1 < SEQT) ? xrow[t + 1] : 0.0f;

        const float* hptr = &sh_h[cur][bl][0];
        #pragma unroll
        for (int q = 0; q < 12; q++) {    // h[0..47]: 12 x 16B shared loads
            const ulonglong2 hv =
                *reinterpret_cast<const ulonglong2*>(hptr + q * 4);
            acc0 = fma2(hv.x, w2[0][2*q],   acc0);
            acc1 = fma2(hv.x, w2[1][2*q],   acc1);
            acc0 = fma2(hv.y, w2[0][2*q+1], acc0);
            acc1 = fma2(hv.y, w2[1][2*q+1], acc1);
        }
        {   // h[48..49]
            const unsigned long long hv =
                *reinterpret_cast<const unsigned long long*>(hptr + 48);
            acc0 = fma2(hv, w2[0][24], acc0);
            acc1 = fma2(hv, w2[1][24], acc1);
        }

        // a0,a1 = pre-activations for this thread's two gates
        const float a0 = hsum2(acc0) + __fmaf_rn(xt, wih[0], bs[0]);
        const float a1 = hsum2(acc1) + __fmaf_rn(xt, wih[1], bs[1]);

        // even thread: v0=sig(i), v1=sig(f); odd thread: v0=tanh(g), v1=sig(o)
        float v0, v1;
        if (gp == 0) { v0 = sigapx(a0);  v1 = sigapx(a1); }
        else         { v0 = tanhapx(a0); v1 = sigapx(a1); }

        // exchange with partner lane (lane^1): even receives tanh(g), sig(o)
        const float p0 = __shfl_xor_sync(0xffffffffu, v0, 1);
        const float p1 = __shfl_xor_sync(0xffffffffu, v1, 1);

        const int nxt = cur ^ 1;
        if (gp == 0) {
            // c = sig(f)*c + sig(i)*tanh(g);  h = sig(o)*tanh(c)
            c = __fmaf_rn(v1, c, v0 * p0);
            const float hn = p1 * tanhapx(c);
            if (active) sh_h[nxt][bl][j] = hn;
        }
        __syncthreads();

        // output projection y_t = h_t . W_out + b_out (one thread per batch elem)
        if (active && r == 0) {
            const float* hp = &sh_h[nxt][bl][0];
            float y0 = bout, y1 = 0.0f, y2 = 0.0f, y3 = 0.0f;
            #pragma unroll
            for (int kq = 0; kq < 13; kq++) {   // pads (50,51) are zero in both
                const float4 hv = *reinterpret_cast<const float4*>(hp + kq * 4);
                const float4 wv = *reinterpret_cast<const float4*>(sh_wout + kq * 4);
                y0 = __fmaf_rn(hv.x, wv.x, y0);
                y1 = __fmaf_rn(hv.y, wv.y, y1);
                y2 = __fmaf_rn(hv.z, wv.z, y2);
                y3 = __fmaf_rn(hv.w, wv.w, y3);
            }
            orow[t] = (y0 + y1) + (y2 + y3);
        }

        xt = xnext;
        cur = nxt;
    }
}

extern "C" void kernel_launch(void* const* d_in, const int* in_sizes, int n_in,
                              void* d_out, int out_size)
{
    const float* x     = (const float*)d_in[0];
    const float* W_ih  = (const float*)d_in[1];
    const float* W_hh  = (const float*)d_in[2];
    const float* b_ih  = (const float*)d_in[3];
    const float* b_hh  = (const float*)d_in[4];
    const float* W_out = (const float*)d_in[5];
    const float* b_out = (const float*)d_in[6];
    float* out = (float*)d_out;

    const int B = in_sizes[0] / SEQT;          // I == 1, x is [B, T, 1]
    const int grid = (B + NB - 1) / NB;
    lstm_fused_kernel<<<grid, BLOCK>>>(x, W_ih, W_hh, b_ih, b_hh, W_out, b_out, out, B);
}

// round 4
// speedup vs baseline: 1.0271x; 1.0271x over previous
#include <cuda_runtime.h>

#define HID   50
#define SEQT  512
#define NB    5          // batch elements per block
#define BLOCK 512        // NB * HID * 2 = 500 active threads
#define ROWP  52         // padded h row (floats), 208B

// packed 2xfp32 FMA: d = a*b + c (elementwise on two floats in a 64-bit reg)
__device__ __forceinline__ unsigned long long fma2(unsigned long long a,
                                                   unsigned long long b,
                                                   unsigned long long c) {
    unsigned long long d;
    asm("fma.rn.f32x2 %0, %1, %2, %3;" : "=l"(d) : "l"(a), "l"(b), "l"(c));
    return d;
}
__device__ __forceinline__ float hsum2(unsigned long long v) {
    float lo, hi;
    asm("mov.b64 {%0, %1}, %2;" : "=f"(lo), "=f"(hi) : "l"(v));
    return lo + hi;
}
__device__ __forceinline__ float tanhapx(float x) {
    float y;
    asm("tanh.approx.f32 %0, %1;" : "=f"(y) : "f"(x));
    return y;
}
__device__ __forceinline__ float sigapx(float x) {
    // sigmoid(x) = 0.5*tanh(x/2) + 0.5   (1 MUFU + 2 FFMA)
    return __fmaf_rn(0.5f, tanhapx(0.5f * x), 0.5f);
}

__global__ void __launch_bounds__(BLOCK, 1)
lstm_fused_kernel(const float* __restrict__ x,
                  const float* __restrict__ W_ih,
                  const float* __restrict__ W_hh,
                  const float* __restrict__ b_ih,
                  const float* __restrict__ b_hh,
                  const float* __restrict__ W_out,
                  const float* __restrict__ b_out,
                  float* __restrict__ out,
                  int B)
{
    // double-buffered hidden state
    __shared__ __align__(16) float sh_h[2][NB][ROWP];
    __shared__ __align__(16) float sh_wout[ROWP];

    const int tid = threadIdx.x;
    int bl = tid / 100;              // local batch index; 5 == filler
    int r  = tid - bl * 100;         // 0..99 within batch element
    const bool lane_ok = (bl < NB);
    if (!lane_ok) { bl = 0; r = 0; } // clamp for safe addressing
    const int j    = r >> 1;         // hidden unit 0..49
    const int half = r & 1;          // k-half: 0 -> k[0,26), 1 -> k[24,50)
    const int b = blockIdx.x * NB + bl;
    const bool active = lane_ok && (b < B);
    const int bb = active ? b : 0;

    // ---- one-time init ----
    for (int i = tid; i < 2 * NB * ROWP; i += BLOCK)
        (&sh_h[0][0][0])[i] = 0.0f;
    if (tid < ROWP)
        sh_wout[tid] = (tid < HID) ? W_out[tid] : 0.0f;

    // This thread's half of W_hh for all 4 gates, as 13 f32-pairs per gate.
    // half 0 covers k=0..25 (pairs p=0..12). half 1 covers k=24..49 with
    // pair p=0 (k=24,25, owned by half 0) zeroed; its base (row*50+24)*4 is
    // 8B-aligned so direct 64-bit loads work.
    unsigned long long w2[4][13];
    float wih[4], bs[4];
    #pragma unroll
    for (int g = 0; g < 4; g++) {
        const int row = g * HID + j;       // PyTorch gate order: i, f, g, o
        wih[g] = W_ih[row];
        bs[g]  = b_ih[row] + b_hh[row];
        const unsigned long long* wrow =
            reinterpret_cast<const unsigned long long*>(W_hh + row * HID + half * 24);
        w2[g][0] = half ? 0ull : wrow[0];
        #pragma unroll
        for (int p = 1; p < 13; p++)
            w2[g][p] = wrow[p];
    }
    const float bout = b_out[0];

    const float* __restrict__ xrow = x   + (size_t)bb * SEQT;
    float*       __restrict__ orow = out + (size_t)bb * SEQT;

    float c  = 0.0f;                 // maintained redundantly in both halves
    float xt = xrow[0];
    int cur = 0;

    __syncthreads();   // h buffer zeroed, wout staged

    for (int t = 0; t < SEQT; t++) {
        unsigned long long acc0 = 0ull, acc1 = 0ull, acc2 = 0ull, acc3 = 0ull;

        // prefetch next x (hidden behind the dot product)
        float xnext = (t + 1 < SEQT) ? xrow[t + 1] : 0.0f;

        // this thread's 26 h values (13 pairs), base 16B-aligned (0 or 96B)
        const float* hbase = &sh_h[cur][bl][half * 24];
        unsigned long long hh[13];
        {
            const ulonglong2* hp2 = reinterpret_cast<const ulonglong2*>(hbase);
            #pragma unroll
            for (int q = 0; q < 6; q++) {
                const ulonglong2 v = hp2[q];
                hh[2*q]   = v.x;
                hh[2*q+1] = v.y;
            }
            hh[12] = reinterpret_cast<const unsigned long long*>(hbase)[12];
        }

        #pragma unroll
        for (int p = 0; p < 13; p++) {
            acc0 = fma2(hh[p], w2[0][p], acc0);
            acc1 = fma2(hh[p], w2[1][p], acc1);
            acc2 = fma2(hh[p], w2[2][p], acc2);
            acc3 = fma2(hh[p], w2[3][p], acc3);
        }

        // horizontal sums, then add partner half's partial dot
        float a0 = hsum2(acc0);
        float a1 = hsum2(acc1);
        float a2 = hsum2(acc2);
        float a3 = hsum2(acc3);
        a0 += __shfl_xor_sync(0xffffffffu, a0, 1);
        a1 += __shfl_xor_sync(0xffffffffu, a1, 1);
        a2 += __shfl_xor_sync(0xffffffffu, a2, 1);
        a3 += __shfl_xor_sync(0xffffffffu, a3, 1);
        // input projection + bias (identical in both halves)
        a0 += __fmaf_rn(xt, wih[0], bs[0]);
        a1 += __fmaf_rn(xt, wih[1], bs[1]);
        a2 += __fmaf_rn(xt, wih[2], bs[2]);
        a3 += __fmaf_rn(xt, wih[3], bs[3]);

        // LSTM cell update, computed redundantly in both halves
        const float ig = sigapx(a0);
        const float fg = sigapx(a1);
        const float gg = tanhapx(a2);
        const float og = sigapx(a3);
        c = __fmaf_rn(fg, c, ig * gg);
        const float hn = og * tanhapx(c);

        const int nxt = cur ^ 1;
        if (active && half == 0) sh_h[nxt][bl][j] = hn;
        __syncthreads();

        // output projection y_t = h_t . W_out + b_out (one thread per batch elem)
        if (active && r == 0) {
            const float* hp = &sh_h[nxt][bl][0];
            float y0 = bout, y1 = 0.0f, y2 = 0.0f, y3 = 0.0f;
            #pragma unroll
            for (int kq = 0; kq < 13; kq++) {   // pads (50,51) are zero in both
                const float4 hv = *reinterpret_cast<const float4*>(hp + kq * 4);
                const float4 wv = *reinterpret_cast<const float4*>(sh_wout + kq * 4);
                y0 = __fmaf_rn(hv.x, wv.x, y0);
                y1 = __fmaf_rn(hv.y, wv.y, y1);
                y2 = __fmaf_rn(hv.z, wv.z, y2);
                y3 = __fmaf_rn(hv.w, wv.w, y3);
            }
            orow[t] = (y0 + y1) + (y2 + y3);
        }

        xt = xnext;
        cur = nxt;
    }
}

extern "C" void kernel_launch(void* const* d_in, const int* in_sizes, int n_in,
                              void* d_out, int out_size)
{
    const float* x     = (const float*)d_in[0];
    const float* W_ih  = (const float*)d_in[1];
    const float* W_hh  = (const float*)d_in[2];
    const float* b_ih  = (const float*)d_in[3];
    const float* b_hh  = (const float*)d_in[4];
    const float* W_out = (const float*)d_in[5];
    const float* b_out = (const float*)d_in[6];
    float* out = (float*)d_out;

    const int B = in_sizes[0] / SEQT;          // I == 1, x is [B, T, 1]
    const int grid = (B + NB - 1) / NB;
    lstm_fused_kernel<<<grid, BLOCK>>>(x, W_ih, W_hh, b_ih, b_hh, W_out, b_out, out, B);
}

// round 5
// speedup vs baseline: 1.1040x; 1.0748x over previous
#include <cuda_runtime.h>

#define HID   50
#define SEQT  512
#define NB    4          // batch elements (groups) per block
#define GROUP 64         // threads per group (2 warps)
#define BLOCK (NB * GROUP)   // 256
#define ROWP  52         // padded h row (floats)

// packed 2xfp32 FMA: d = a*b + c
__device__ __forceinline__ unsigned long long fma2(unsigned long long a,
                                                   unsigned long long b,
                                                   unsigned long long c) {
    unsigned long long d;
    asm("fma.rn.f32x2 %0, %1, %2, %3;" : "=l"(d) : "l"(a), "l"(b), "l"(c));
    return d;
}
__device__ __forceinline__ float hsum2(unsigned long long v) {
    float lo, hi;
    asm("mov.b64 {%0, %1}, %2;" : "=f"(lo), "=f"(hi) : "l"(v));
    return lo + hi;
}
__device__ __forceinline__ float tanhapx(float x) {
    float y;
    asm("tanh.approx.f32 %0, %1;" : "=f"(y) : "f"(x));
    return y;
}
__device__ __forceinline__ float sigapx(float x) {
    return __fmaf_rn(0.5f, tanhapx(0.5f * x), 0.5f);
}
// named barrier over `cnt` threads (2 warps of one group)
__device__ __forceinline__ void group_bar(int id) {
    asm volatile("bar.sync %0, %1;" :: "r"(id), "n"(GROUP) : "memory");
}

__global__ void __launch_bounds__(BLOCK, 1)
lstm_fused_kernel(const float* __restrict__ x,
                  const float* __restrict__ W_ih,
                  const float* __restrict__ W_hh,
                  const float* __restrict__ b_ih,
                  const float* __restrict__ b_hh,
                  const float* __restrict__ W_out,
                  const float* __restrict__ b_out,
                  float* __restrict__ out,
                  int B)
{
    __shared__ __align__(16) float sh_h[2][NB][ROWP];   // double-buffered h
    __shared__ __align__(16) float sh_wout[ROWP];

    const int tid = threadIdx.x;
    const int g   = tid >> 6;        // group / local batch index 0..3
    const int r   = tid & 63;        // lane within group
    const int j   = r;               // hidden unit (valid when r < 50)
    const int b   = blockIdx.x * NB + g;
    const bool active = (b < B);
    const int bb = active ? b : 0;
    const bool gate_th = active && (r < HID);
    const bool out_th  = active && (r == HID);

    // ---- one-time init ----
    for (int i = tid; i < 2 * NB * ROWP; i += BLOCK)
        (&sh_h[0][0][0])[i] = 0.0f;
    if (tid < ROWP)
        sh_wout[tid] = (tid < HID) ? W_out[tid] : 0.0f;

    // gate threads: 4 W_hh rows in registers as f32 pairs (row base 8B-aligned)
    unsigned long long w2[4][25];
    float wih[4], bs[4];
    if (gate_th) {
        #pragma unroll
        for (int gg = 0; gg < 4; gg++) {
            const int row = gg * HID + j;     // PyTorch gate order: i, f, g, o
            wih[gg] = W_ih[row];
            bs[gg]  = b_ih[row] + b_hh[row];
            const unsigned long long* wrow =
                reinterpret_cast<const unsigned long long*>(W_hh + row * HID);
            #pragma unroll
            for (int p = 0; p < 25; p++)
                w2[gg][p] = wrow[p];
        }
    }
    const float bout = b_out[0];

    const float* __restrict__ xrow = x   + (size_t)bb * SEQT;
    float*       __restrict__ orow = out + (size_t)bb * SEQT;

    float c  = 0.0f;
    float xt = gate_th ? xrow[0] : 0.0f;
    int cur = 0;

    __syncthreads();   // h zeroed, wout staged (block-wide, once)

    const int barid = g + 1;   // named barrier ids 1..4

    for (int t = 0; t < SEQT; t++) {
        const int nxt = cur ^ 1;

        if (gate_th) {
            unsigned long long acc0 = 0ull, acc1 = 0ull, acc2 = 0ull, acc3 = 0ull;
            float xnext = (t + 1 < SEQT) ? xrow[t + 1] : 0.0f;

            const float* hptr = &sh_h[cur][g][0];
            #pragma unroll
            for (int q = 0; q < 12; q++) {        // h[0..47]
                const ulonglong2 hv =
                    *reinterpret_cast<const ulonglong2*>(hptr + q * 4);
                acc0 = fma2(hv.x, w2[0][2*q],   acc0);
                acc1 = fma2(hv.x, w2[1][2*q],   acc1);
                acc2 = fma2(hv.x, w2[2][2*q],   acc2);
                acc3 = fma2(hv.x, w2[3][2*q],   acc3);
                acc0 = fma2(hv.y, w2[0][2*q+1], acc0);
                acc1 = fma2(hv.y, w2[1][2*q+1], acc1);
                acc2 = fma2(hv.y, w2[2][2*q+1], acc2);
                acc3 = fma2(hv.y, w2[3][2*q+1], acc3);
            }
            {   // h[48..49]
                const unsigned long long hv =
                    *reinterpret_cast<const unsigned long long*>(hptr + 48);
                acc0 = fma2(hv, w2[0][24], acc0);
                acc1 = fma2(hv, w2[1][24], acc1);
                acc2 = fma2(hv, w2[2][24], acc2);
                acc3 = fma2(hv, w2[3][24], acc3);
            }

            const float a0 = hsum2(acc0) + __fmaf_rn(xt, wih[0], bs[0]);
            const float a1 = hsum2(acc1) + __fmaf_rn(xt, wih[1], bs[1]);
            const float a2 = hsum2(acc2) + __fmaf_rn(xt, wih[2], bs[2]);
            const float a3 = hsum2(acc3) + __fmaf_rn(xt, wih[3], bs[3]);

            const float ig = sigapx(a0);
            const float fg = sigapx(a1);
            const float gg = tanhapx(a2);
            const float og = sigapx(a3);
            c = __fmaf_rn(fg, c, ig * gg);
            const float hn = og * tanhapx(c);

            sh_h[nxt][g][j] = hn;
            xt = xnext;
        } else if (out_th && t > 0) {
            // out[t-1] = h_{t-1} . W_out + b_out ; h_{t-1} lives in buf[cur].
            // Runs concurrently with the gate threads' dot (read-read overlap).
            const float* hp = &sh_h[cur][g][0];
            float y0 = bout, y1 = 0.0f, y2 = 0.0f, y3 = 0.0f;
            #pragma unroll
            for (int kq = 0; kq < 13; kq++) {     // pads are zero in both
                const float4 hv = *reinterpret_cast<const float4*>(hp + kq * 4);
                const float4 wv = *reinterpret_cast<const float4*>(sh_wout + kq * 4);
                y0 = __fmaf_rn(hv.x, wv.x, y0);
                y1 = __fmaf_rn(hv.y, wv.y, y1);
                y2 = __fmaf_rn(hv.z, wv.z, y2);
                y3 = __fmaf_rn(hv.w, wv.w, y3);
            }
            orow[t - 1] = (y0 + y1) + (y2 + y3);
        }

        group_bar(barid);    // only this group's 2 warps
        cur = nxt;
    }

    // final output element: h_{T-1} is in buf[cur]
    if (out_th) {
        const float* hp = &sh_h[cur][g][0];
        float y0 = bout, y1 = 0.0f, y2 = 0.0f, y3 = 0.0f;
        #pragma unroll
        for (int kq = 0; kq < 13; kq++) {
            const float4 hv = *reinterpret_cast<const float4*>(hp + kq * 4);
            const float4 wv = *reinterpret_cast<const float4*>(sh_wout + kq * 4);
            y0 = __fmaf_rn(hv.x, wv.x, y0);
            y1 = __fmaf_rn(hv.y, wv.y, y1);
            y2 = __fmaf_rn(hv.z, wv.z, y2);
            y3 = __fmaf_rn(hv.w, wv.w, y3);
        }
        orow[SEQT - 1] = (y0 + y1) + (y2 + y3);
    }
}

extern "C" void kernel_launch(void* const* d_in, const int* in_sizes, int n_in,
                              void* d_out, int out_size)
{
    const float* x     = (const float*)d_in[0];
    const float* W_ih  = (const float*)d_in[1];
    const float* W_hh  = (const float*)d_in[2];
    const float* b_ih  = (const float*)d_in[3];
    const float* b_hh  = (const float*)d_in[4];
    const float* W_out = (const float*)d_in[5];
    const float* b_out = (const float*)d_in[6];
    float* out = (float*)d_out;

    const int B = in_sizes[0] / SEQT;          // I == 1, x is [B, T, 1]
    const int grid = (B + NB - 1) / NB;
    lstm_fused_kernel<<<grid, BLOCK>>>(x, W_ih, W_hh, b_ih, b_hh, W_out, b_out, out, B);
}